// round 5
// baseline (speedup 1.0000x reference)
#include <cuda_runtime.h>
#include <math.h>

// Problem dims
#define BB   64      // batch
#define TT   512     // seq len
#define EE   256     // embed
#define HH   512     // hidden
#define GG   2048    // 4*HH
#define KC   64      // k rows per staged chunk (32 k-pairs)

// SMEM tiles, k-pair interleaved:
//   wt[kp][col][2] : 32 cols -> 64 floats/row, pad to 68 (272B rows, 16B aligned)
//   ht[kp][b][2]   : 64 b    -> 128 floats/row, pad to 132 (528B rows, 16B aligned)
#define WP   68
#define HP   132
#define WTF  (32 * WP)     // 2176 floats per buffer
#define HTF  (32 * HP)     // 4224 floats per buffer
#define ZBF  (32 * BB)     // 2048 floats
#define SMEM_BYTES ((2*WTF + 2*HTF + ZBF) * 4)   // 59392

// ---------------- device scratch (allocation-free) ----------------
__device__ float g_X[TT * EE * BB];        // [t][e][b]
__device__ float g_h1[2][2][HH * BB];      // [dir][parity][k][b]
__device__ float g_h2[2][2][HH * BB];
__device__ unsigned g_bar[2];
__device__ int g_tok32;

// ---------------- helpers ----------------
__device__ __forceinline__ float fsig(float x) { return 1.0f / (1.0f + __expf(-x)); }
__device__ __forceinline__ float ftanh(float x) {
    return 2.0f / (1.0f + __expf(-2.0f * x)) - 1.0f;
}

__device__ __forceinline__ void ffma2(unsigned long long& d,
                                      unsigned long long a,
                                      unsigned long long b) {
    asm("fma.rn.f32x2 %0, %1, %2, %0;" : "+l"(d) : "l"(a), "l"(b));
}

__device__ __forceinline__ void grid_bar(unsigned* ctr, unsigned target) {
    __syncthreads();
    if (threadIdx.x == 0) {
        __threadfence();
        atomicAdd(ctr, 1u);
        while (*((volatile unsigned*)ctr) < target) { }
    }
    __syncthreads();
}

// ---------------- reset ----------------
__global__ void reset_kernel() {
    int i = blockIdx.x * blockDim.x + threadIdx.x;
    if (i < HH * BB) {
        #pragma unroll
        for (int d = 0; d < 2; d++)
            #pragma unroll
            for (int p = 0; p < 2; p++) { g_h1[d][p][i] = 0.0f; g_h2[d][p][i] = 0.0f; }
    }
    if (i == 0) { g_bar[0] = 0u; g_bar[1] = 0u; }
}

// ---------------- token dtype detect ----------------
__global__ void detect_kernel(const unsigned* tok) {
    __shared__ unsigned red[256];
    unsigned v = 0;
    for (int i = threadIdx.x; i < 16384; i += 256) v |= tok[2 * i + 1];
    red[threadIdx.x] = v;
    __syncthreads();
    for (int s = 128; s > 0; s >>= 1) {
        if (threadIdx.x < s) red[threadIdx.x] |= red[threadIdx.x + s];
        __syncthreads();
    }
    if (threadIdx.x == 0) g_tok32 = (red[0] != 0u) ? 1 : 0;
}

// ---------------- embedding gather (X[t][e][b]) ----------------
__global__ void gather_kernel(const void* tokens, const float* emb) {
    int t = blockIdx.x;
    int b = blockIdx.y;
    int e = threadIdx.x;
    long idx;
    if (g_tok32) idx = (long)((const int*)tokens)[b * TT + t];
    else         idx = (long)((const unsigned*)tokens)[(size_t)(b * TT + t) * 2];
    g_X[((size_t)t * EE + e) * BB + b] = emb[idx * EE + e];
}

// ---------------- staging fragments (256 threads) ----------------
// thread: s2 = tid>>3 (k-pair row 0..31), g8 = tid&7 (group 0..7)
// w: group = col-quad (4 cols);  h: group = b-octet (8 batches)
struct WStage { float4 a, b; };           // 4 cols x 2 k
struct HStage { float4 e0, e1, o0, o1; }; // 8 b x 2 k

__device__ __forceinline__ void load_w(WStage& s, const float* __restrict__ Wg,
                                       int k0, int s2, int gcol) {
    const float* p = Wg + (size_t)(k0 + 2 * s2) * GG + gcol;
    s.a = *(const float4*)p;
    s.b = *(const float4*)(p + GG);
}
__device__ __forceinline__ void store_w(const WStage& s, float* wt, int s2, int g8) {
    float* d = wt + s2 * WP + g8 * 8;
    ((float4*)d)[0] = make_float4(s.a.x, s.b.x, s.a.y, s.b.y);
    ((float4*)d)[1] = make_float4(s.a.z, s.b.z, s.a.w, s.b.w);
}
__device__ __forceinline__ void load_h(HStage& s, const float* __restrict__ src,
                                       int k0, int s2, int g8) {
    const float* p = src + (size_t)(k0 + 2 * s2) * BB + 8 * g8;
    s.e0 = __ldcg((const float4*)p);
    s.e1 = __ldcg((const float4*)(p + 4));
    s.o0 = __ldcg((const float4*)(p + BB));
    s.o1 = __ldcg((const float4*)(p + BB + 4));
}
__device__ __forceinline__ void store_h(const HStage& s, float* ht, int s2, int g8) {
    float* d = ht + s2 * HP + g8 * 16;
    ((float4*)d)[0] = make_float4(s.e0.x, s.o0.x, s.e0.y, s.o0.y);
    ((float4*)d)[1] = make_float4(s.e0.z, s.o0.z, s.e0.w, s.o0.w);
    ((float4*)d)[2] = make_float4(s.e1.x, s.o1.x, s.e1.y, s.o1.y);
    ((float4*)d)[3] = make_float4(s.e1.z, s.o1.z, s.e1.w, s.o1.w);
}

// ---------------- inner compute: one 64-k chunk, 8 cols x 1 b per thread ----------
__device__ __forceinline__ void compute_chunk(unsigned long long acc2[8],
                                              const float* wt, const float* ht,
                                              int b, int cg) {
    #pragma unroll 16
    for (int kp = 0; kp < KC / 2; kp++) {
        unsigned long long hv = *(const unsigned long long*)(ht + kp * HP + 2 * b);
        const float* wrow = wt + kp * WP + cg * 16;
        ulonglong2 w0 = *(const ulonglong2*)wrow;        // cols 0,1
        ulonglong2 w1 = *(const ulonglong2*)(wrow + 4);  // cols 2,3
        ulonglong2 w2 = *(const ulonglong2*)(wrow + 8);  // cols 4,5
        ulonglong2 w3 = *(const ulonglong2*)(wrow + 12); // cols 6,7
        ffma2(acc2[0], w0.x, hv); ffma2(acc2[1], w0.y, hv);
        ffma2(acc2[2], w1.x, hv); ffma2(acc2[3], w1.y, hv);
        ffma2(acc2[4], w2.x, hv); ffma2(acc2[5], w2.y, hv);
        ffma2(acc2[6], w3.x, hv); ffma2(acc2[7], w3.y, hv);
    }
}

// ---------------- pipelined GEMM: acc += src^T @ W slice ----------------
__device__ __forceinline__ void gemm_pipe(unsigned long long acc2[8],
    const float* __restrict__ src, int nk, const float* __restrict__ Wg, int ub,
    int tid, int b, int cg,
    float* wt0, float* wt1, float* ht0, float* ht1)
{
    const int s2 = tid >> 3;        // k-pair row 0..31
    const int g8 = tid & 7;         // staging group 0..7
    const int gcol = (g8 >> 1) * HH + ub + (g8 & 1) * 4;
    const int n = nk / KC;

    WStage ws; HStage hs;
    load_w(ws, Wg, 0, s2, gcol);
    load_h(hs, src, 0, s2, g8);
    store_w(ws, wt0, s2, g8);
    store_h(hs, ht0, s2, g8);
    __syncthreads();
    for (int c = 0; c < n; c++) {
        const float* wtc = (c & 1) ? wt1 : wt0;
        const float* htc = (c & 1) ? ht1 : ht0;
        float* wtn = (c & 1) ? wt0 : wt1;
        float* htn = (c & 1) ? ht0 : ht1;
        if (c + 1 < n) {
            load_w(ws, Wg, (c + 1) * KC, s2, gcol);
            load_h(hs, src, (c + 1) * KC, s2, g8);
        }
        compute_chunk(acc2, wtc, htc, b, cg);
        if (c + 1 < n) {
            store_w(ws, wtn, s2, g8);
            store_h(hs, htn, s2, g8);
        }
        __syncthreads();
    }
}

// ---------------- persistent BiLSTM kernel ----------------
__global__ void __launch_bounds__(256, 1) lstm_kernel(
    const float* __restrict__ W1f, const float* __restrict__ U1f, const float* __restrict__ b1f,
    const float* __restrict__ W2f, const float* __restrict__ U2f, const float* __restrict__ b2f,
    const float* __restrict__ W1b, const float* __restrict__ U1b, const float* __restrict__ b1b,
    const float* __restrict__ W2b, const float* __restrict__ U2b, const float* __restrict__ b2b)
{
    const int dir = blockIdx.x >> 6;
    const int cid = blockIdx.x & 63;
    const int ub  = cid * 8;             // 8 hidden units -> 32 gate cols
    const int tid = threadIdx.x;
    const int b   = tid & 63;            // batch lane
    const int cg  = tid >> 6;            // gate 0..3 (8 cols each)

    const float *W1, *U1, *b1, *W2, *U2, *b2;
    if (dir == 0) { W1 = W1f; U1 = U1f; b1 = b1f; W2 = W2f; U2 = U2f; b2 = b2f; }
    else          { W1 = W1b; U1 = U1b; b1 = b1b; W2 = W2b; U2 = U2b; b2 = b2b; }

    extern __shared__ float smem[];
    float* wt0 = smem;
    float* wt1 = wt0 + WTF;
    float* ht0 = wt1 + WTF;
    float* ht1 = ht0 + HTF;
    float* zb  = ht1 + HTF;              // [32 local cols: gate*8+u][64 b]

    const float4 b1v0 = *(const float4*)(b1 + cg * HH + ub);
    const float4 b1v1 = *(const float4*)(b1 + cg * HH + ub + 4);
    const float4 b2v0 = *(const float4*)(b2 + cg * HH + ub);
    const float4 b2v1 = *(const float4*)(b2 + cg * HH + ub + 4);

    // pointwise: thread owns (u=tid>>6, b) and (u+4, b)
    float c1_0 = 0.0f, c1_1 = 0.0f, c2_0 = 0.0f, c2_1 = 0.0f;
    unsigned target = 0;
    float* h1w[2] = { g_h1[dir][0], g_h1[dir][1] };
    float* h2w[2] = { g_h2[dir][0], g_h2[dir][1] };

    for (int t = 0; t < TT; t++) {
        const int ttx = dir ? (TT - 1 - t) : t;
        const int wp = t & 1, rp = wp ^ 1;

        // ================= Phase A: layer 1 =================
        unsigned long long acc2[8];
        #pragma unroll
        for (int j = 0; j < 8; j++) acc2[j] = 0ull;
        gemm_pipe(acc2, g_X + (size_t)ttx * EE * BB, EE, W1, ub, tid, b, cg, wt0, wt1, ht0, ht1);
        gemm_pipe(acc2, h1w[rp], HH, U1, ub, tid, b, cg, wt0, wt1, ht0, ht1);

        {
            const float* bp0 = (const float*)&b1v0;
            const float* bp1 = (const float*)&b1v1;
            #pragma unroll
            for (int j = 0; j < 8; j++) {
                float lo = __int_as_float((int)(acc2[j] & 0xffffffffull));
                float hi = __int_as_float((int)(acc2[j] >> 32));
                float bias = (j < 4) ? bp0[j] : bp1[j - 4];
                zb[(cg * 8 + j) * BB + b] = lo + hi + bias;
            }
        }
        __syncthreads();
        {
            int u = tid >> 6, bb2 = tid & 63;
            float iv = zb[( 0 + u) * BB + bb2];
            float fv = zb[( 8 + u) * BB + bb2];
            float gv = zb[(16 + u) * BB + bb2];
            float ov = zb[(24 + u) * BB + bb2];
            c1_0 = fsig(fv) * c1_0 + fsig(iv) * ftanh(gv);
            __stcg(&h1w[wp][(ub + u) * BB + bb2], fsig(ov) * ftanh(c1_0));
            u += 4;
            iv = zb[( 0 + u) * BB + bb2];
            fv = zb[( 8 + u) * BB + bb2];
            gv = zb[(16 + u) * BB + bb2];
            ov = zb[(24 + u) * BB + bb2];
            c1_1 = fsig(fv) * c1_1 + fsig(iv) * ftanh(gv);
            __stcg(&h1w[wp][(ub + u) * BB + bb2], fsig(ov) * ftanh(c1_1));
        }
        target += 64;
        grid_bar(&g_bar[dir], target);

        // ================= Phase B: layer 2 =================
        #pragma unroll
        for (int j = 0; j < 8; j++) acc2[j] = 0ull;
        gemm_pipe(acc2, h1w[wp], HH, W2, ub, tid, b, cg, wt0, wt1, ht0, ht1);
        gemm_pipe(acc2, h2w[rp], HH, U2, ub, tid, b, cg, wt0, wt1, ht0, ht1);

        {
            const float* bp0 = (const float*)&b2v0;
            const float* bp1 = (const float*)&b2v1;
            #pragma unroll
            for (int j = 0; j < 8; j++) {
                float lo = __int_as_float((int)(acc2[j] & 0xffffffffull));
                float hi = __int_as_float((int)(acc2[j] >> 32));
                float bias = (j < 4) ? bp0[j] : bp1[j - 4];
                zb[(cg * 8 + j) * BB + b] = lo + hi + bias;
            }
        }
        __syncthreads();
        {
            int u = tid >> 6, bb2 = tid & 63;
            float iv = zb[( 0 + u) * BB + bb2];
            float fv = zb[( 8 + u) * BB + bb2];
            float gv = zb[(16 + u) * BB + bb2];
            float ov = zb[(24 + u) * BB + bb2];
            c2_0 = fsig(fv) * c2_0 + fsig(iv) * ftanh(gv);
            __stcg(&h2w[wp][(ub + u) * BB + bb2], fsig(ov) * ftanh(c2_0));
            u += 4;
            iv = zb[( 0 + u) * BB + bb2];
            fv = zb[( 8 + u) * BB + bb2];
            gv = zb[(16 + u) * BB + bb2];
            ov = zb[(24 + u) * BB + bb2];
            c2_1 = fsig(fv) * c2_1 + fsig(iv) * ftanh(gv);
            __stcg(&h2w[wp][(ub + u) * BB + bb2], fsig(ov) * ftanh(c2_1));
        }
        target += 64;
        grid_bar(&g_bar[dir], target);
    }
}

// ---------------- final dense head ----------------
__global__ void dense_kernel(const float* __restrict__ Wd, const float* __restrict__ bd,
                             float* __restrict__ out) {
    int tid = threadIdx.x;
    if (tid >= 320) return;
    int bb2 = tid / 5, o = tid % 5;
    float s = bd[o];
    for (int j = 0; j < HH; j++) s += g_h2[0][1][j * BB + bb2] * Wd[j * 5 + o];
    for (int j = 0; j < HH; j++) s += g_h2[1][1][j * BB + bb2] * Wd[(HH + j) * 5 + o];
    out[bb2 * 5 + o] = s;
}

// ---------------- launch ----------------
extern "C" void kernel_launch(void* const* d_in, const int* in_sizes, int n_in,
                              void* d_out, int out_size) {
    const void*  tokens = d_in[0];
    const float* emb = (const float*)d_in[1];
    const float* W1f = (const float*)d_in[2];
    const float* U1f = (const float*)d_in[3];
    const float* b1f = (const float*)d_in[4];
    const float* W2f = (const float*)d_in[5];
    const float* U2f = (const float*)d_in[6];
    const float* b2f = (const float*)d_in[7];
    const float* W1b = (const float*)d_in[8];
    const float* U1b = (const float*)d_in[9];
    const float* b1b = (const float*)d_in[10];
    const float* W2b = (const float*)d_in[11];
    const float* U2b = (const float*)d_in[12];
    const float* b2b = (const float*)d_in[13];
    const float* Wd  = (const float*)d_in[14];
    const float* bd  = (const float*)d_in[15];
    float* out = (float*)d_out;

    cudaFuncSetAttribute(lstm_kernel, cudaFuncAttributeMaxDynamicSharedMemorySize, SMEM_BYTES);

    reset_kernel<<<128, 256>>>();
    detect_kernel<<<1, 256>>>((const unsigned*)tokens);
    dim3 gg(TT, BB);
    gather_kernel<<<gg, 256>>>(tokens, emb);
    lstm_kernel<<<128, 256, SMEM_BYTES>>>(W1f, U1f, b1f, W2f, U2f, b2f,
                                          W1b, U1b, b1b, W2b, U2b, b2b);
    dense_kernel<<<1, 320>>>(Wd, bd, out);
}

// round 6
// speedup vs baseline: 1.1270x; 1.1270x over previous
#include <cuda_runtime.h>
#include <math.h>

// Problem dims
#define BB   64      // batch
#define TT   512     // seq len
#define EE   256     // embed
#define HH   512     // hidden
#define GG   2048    // 4*HH
#define KC   64      // k rows per staged chunk
#define WSTR 36      // wt row stride in floats (144B, 16B-aligned)

// SMEM (floats): per half, double-buffered wt + ht; plus zb (final) + zbp (partial)
#define WTF  (KC * WSTR)   // 2304
#define HTF  (KC * BB)     // 4096
#define ZBF  (32 * BB)     // 2048
#define SMEM_FLOATS (2*2*WTF + 2*2*HTF + 2*ZBF)
#define SMEM_BYTES  (SMEM_FLOATS * 4)   // 118784

// ---------------- device scratch (allocation-free) ----------------
__device__ float g_X[TT * EE * BB];        // [t][e][b]
__device__ float g_h1[2][2][HH * BB];      // [dir][parity][k][b]
__device__ float g_h2[2][2][HH * BB];
__device__ unsigned g_bar[2];
__device__ int g_tok32;

// ---------------- helpers ----------------
__device__ __forceinline__ float fsig(float x) { return 1.0f / (1.0f + __expf(-x)); }
__device__ __forceinline__ float ftanh(float x) {
    return 2.0f / (1.0f + __expf(-2.0f * x)) - 1.0f;
}

__device__ __forceinline__ void ffma2(unsigned long long& d,
                                      unsigned long long a,
                                      unsigned long long b) {
    asm("fma.rn.f32x2 %0, %1, %2, %0;" : "+l"(d) : "l"(a), "l"(b));
}

__device__ __forceinline__ void grid_bar(unsigned* ctr, unsigned target) {
    __syncthreads();
    if (threadIdx.x == 0) {
        __threadfence();
        atomicAdd(ctr, 1u);
        while (*((volatile unsigned*)ctr) < target) { }
    }
    __syncthreads();
}

// ---------------- reset ----------------
__global__ void reset_kernel() {
    int i = blockIdx.x * blockDim.x + threadIdx.x;
    if (i < HH * BB) {
        #pragma unroll
        for (int d = 0; d < 2; d++)
            #pragma unroll
            for (int p = 0; p < 2; p++) { g_h1[d][p][i] = 0.0f; g_h2[d][p][i] = 0.0f; }
    }
    if (i == 0) { g_bar[0] = 0u; g_bar[1] = 0u; }
}

// ---------------- token dtype detect ----------------
__global__ void detect_kernel(const unsigned* tok) {
    __shared__ unsigned red[256];
    unsigned v = 0;
    for (int i = threadIdx.x; i < 16384; i += 256) v |= tok[2 * i + 1];
    red[threadIdx.x] = v;
    __syncthreads();
    for (int s = 128; s > 0; s >>= 1) {
        if (threadIdx.x < s) red[threadIdx.x] |= red[threadIdx.x + s];
        __syncthreads();
    }
    if (threadIdx.x == 0) g_tok32 = (red[0] != 0u) ? 1 : 0;
}

// ---------------- embedding gather (X[t][e][b]) ----------------
__global__ void gather_kernel(const void* tokens, const float* emb) {
    int t = blockIdx.x;
    int b = blockIdx.y;
    int e = threadIdx.x;
    long idx;
    if (g_tok32) idx = (long)((const int*)tokens)[b * TT + t];
    else         idx = (long)((const unsigned*)tokens)[(size_t)(b * TT + t) * 2];
    g_X[((size_t)t * EE + e) * BB + b] = emb[idx * EE + e];
}

// ---------------- staging (256 threads per half, R2 layout) ----------------
struct WStage { float4 a, b; };             // 8 cols of one gate, one k row
struct HStage { float4 v0, v1, v2, v3; };   // 16 consecutive floats of h chunk

__device__ __forceinline__ void load_w(WStage& s, const float* __restrict__ Wg,
                                       int k0, int skl, int sseg, int ub) {
    const float4* p = (const float4*)(Wg + (size_t)(k0 + skl) * GG + sseg * HH + ub);
    s.a = p[0];
    s.b = p[1];
}
__device__ __forceinline__ void store_w(const WStage& s, float* wt, int skl, int sseg) {
    float4* d = (float4*)(wt + skl * WSTR + sseg * 8);
    d[0] = s.a;
    d[1] = s.b;
}
__device__ __forceinline__ void load_h(HStage& s, const float* __restrict__ src,
                                       int k0, int htid) {
    const float4* p = (const float4*)(src + (size_t)k0 * BB);
    s.v0 = __ldcg(p + htid);
    s.v1 = __ldcg(p + htid + 256);
    s.v2 = __ldcg(p + htid + 512);
    s.v3 = __ldcg(p + htid + 768);
}
__device__ __forceinline__ void store_h(const HStage& s, float* ht, int htid) {
    float4* d = (float4*)ht;
    d[htid      ] = s.v0;
    d[htid + 256] = s.v1;
    d[htid + 512] = s.v2;
    d[htid + 768] = s.v3;
}

// ---------------- inner compute: one 64-k chunk, col-pair f32x2 ----------------
__device__ __forceinline__ void compute_chunk(unsigned long long acc2[4],
                                              const float* wt, const float* ht,
                                              int b, int cg) {
    #pragma unroll 16
    for (int k = 0; k < KC; k++) {
        unsigned hv = __float_as_uint(ht[k * BB + b]);
        unsigned long long hd;
        asm("mov.b64 %0, {%1, %1};" : "=l"(hd) : "r"(hv));
        const ulonglong2* w = (const ulonglong2*)(wt + k * WSTR + cg * 8);
        ulonglong2 w0 = w[0];            // cols (0,1),(2,3)
        ulonglong2 w1 = w[1];            // cols (4,5),(6,7)
        ffma2(acc2[0], w0.x, hd);
        ffma2(acc2[1], w0.y, hd);
        ffma2(acc2[2], w1.x, hd);
        ffma2(acc2[3], w1.y, hd);
    }
}

// ---------------- pipelined GEMM with k-split halves ----------------
// This half processes chunks c = half, half+2, ... (nk/KC is even for all calls)
__device__ __forceinline__ void gemm_pipe(unsigned long long acc2[4],
    const float* __restrict__ src, int nk, const float* __restrict__ Wg, int ub,
    int htid, int b, int cg, int half,
    float* wt0, float* wt1, float* ht0, float* ht1)
{
    const int skl  = htid & 63;     // k row staged by this thread
    const int sseg = htid >> 6;     // gate segment staged (8 cols)
    const int nit  = (nk / KC) >> 1;

    WStage ws; HStage hs;
    int c = half;
    load_w(ws, Wg, c * KC, skl, sseg, ub);
    load_h(hs, src, c * KC, htid);
    store_w(ws, wt0, skl, sseg);
    store_h(hs, ht0, htid);
    __syncthreads();
    for (int i = 0; i < nit; i++) {
        const float* wtc = (i & 1) ? wt1 : wt0;
        const float* htc = (i & 1) ? ht1 : ht0;
        float* wtn = (i & 1) ? wt0 : wt1;
        float* htn = (i & 1) ? ht0 : ht1;
        if (i + 1 < nit) {
            load_w(ws, Wg, (c + 2) * KC, skl, sseg, ub);
            load_h(hs, src, (c + 2) * KC, htid);
        }
        compute_chunk(acc2, wtc, htc, b, cg);
        if (i + 1 < nit) {
            store_w(ws, wtn, skl, sseg);
            store_h(hs, htn, htid);
        }
        __syncthreads();
        c += 2;
    }
}

// ---------------- persistent BiLSTM kernel (512 threads) ----------------
__global__ void __launch_bounds__(512, 1) lstm_kernel(
    const float* __restrict__ W1f, const float* __restrict__ U1f, const float* __restrict__ b1f,
    const float* __restrict__ W2f, const float* __restrict__ U2f, const float* __restrict__ b2f,
    const float* __restrict__ W1b, const float* __restrict__ U1b, const float* __restrict__ b1b,
    const float* __restrict__ W2b, const float* __restrict__ U2b, const float* __restrict__ b2b)
{
    const int dir  = blockIdx.x >> 6;
    const int cid  = blockIdx.x & 63;
    const int ub   = cid * 8;            // 8 hidden units -> 32 gate cols
    const int tid  = threadIdx.x;
    const int half = tid >> 8;           // k-split half 0/1
    const int htid = tid & 255;
    const int b    = htid & 63;          // batch lane
    const int cg   = htid >> 6;          // gate 0..3

    const float *W1, *U1, *b1, *W2, *U2, *b2;
    if (dir == 0) { W1 = W1f; U1 = U1f; b1 = b1f; W2 = W2f; U2 = U2f; b2 = b2f; }
    else          { W1 = W1b; U1 = U1b; b1 = b1b; W2 = W2b; U2 = U2b; b2 = b2b; }

    extern __shared__ float smem[];
    float* wtA0 = smem;                   // half 0 buffers
    float* wtA1 = wtA0 + WTF;
    float* wtB0 = wtA1 + WTF;             // half 1 buffers
    float* wtB1 = wtB0 + WTF;
    float* htA0 = wtB1 + WTF;
    float* htA1 = htA0 + HTF;
    float* htB0 = htA1 + HTF;
    float* htB1 = htB0 + HTF;
    float* zb   = htB1 + HTF;             // [32 local cols][64 b] final
    float* zbp  = zb + ZBF;               // partial (half 1)

    float* wt0 = half ? wtB0 : wtA0;
    float* wt1 = half ? wtB1 : wtA1;
    float* ht0 = half ? htB0 : htA0;
    float* ht1 = half ? htB1 : htA1;

    // bias (8 cols of gate cg)
    const float4 b1v0 = *(const float4*)(b1 + cg * HH + ub);
    const float4 b1v1 = *(const float4*)(b1 + cg * HH + ub + 4);
    const float4 b2v0 = *(const float4*)(b2 + cg * HH + ub);
    const float4 b2v1 = *(const float4*)(b2 + cg * HH + ub + 4);

    // pointwise: thread owns one (u, b) per layer
    const int pu = tid >> 6 & 7;   // same as (tid>>6) mod 8: 512 threads -> u 0..7 x b 0..63
    const int pb = tid & 63;
    const int zr = pu * BB + pb;   // gate g row offset = (g*8+pu)*BB+pb = zr + g*8*BB
    float c1 = 0.0f, c2 = 0.0f;
    unsigned target = 0;
    float* h1w[2] = { g_h1[dir][0], g_h1[dir][1] };
    float* h2w[2] = { g_h2[dir][0], g_h2[dir][1] };

    for (int t = 0; t < TT; t++) {
        const int ttx = dir ? (TT - 1 - t) : t;
        const int wp = t & 1, rp = wp ^ 1;

        // ================= Phase A: layer 1 =================
        unsigned long long acc2[4];
        #pragma unroll
        for (int j = 0; j < 4; j++) acc2[j] = 0ull;
        gemm_pipe(acc2, g_X + (size_t)ttx * EE * BB, EE, W1, ub, htid, b, cg, half,
                  wt0, wt1, ht0, ht1);
        gemm_pipe(acc2, h1w[rp], HH, U1, ub, htid, b, cg, half,
                  wt0, wt1, ht0, ht1);

        if (half == 1) {
            #pragma unroll
            for (int j = 0; j < 4; j++) {
                zbp[(cg * 8 + 2 * j    ) * BB + b] = __int_as_float((int)(acc2[j] & 0xffffffffull));
                zbp[(cg * 8 + 2 * j + 1) * BB + b] = __int_as_float((int)(acc2[j] >> 32));
            }
        }
        __syncthreads();
        if (half == 0) {
            const float* bp0 = (const float*)&b1v0;
            const float* bp1 = (const float*)&b1v1;
            #pragma unroll
            for (int j = 0; j < 4; j++) {
                float lo = __int_as_float((int)(acc2[j] & 0xffffffffull));
                float hi = __int_as_float((int)(acc2[j] >> 32));
                int je = 2 * j, jo = 2 * j + 1;
                float be = (je < 4) ? bp0[je] : bp1[je - 4];
                float bo = (jo < 4) ? bp0[jo] : bp1[jo - 4];
                zb[(cg * 8 + je) * BB + b] = lo + zbp[(cg * 8 + je) * BB + b] + be;
                zb[(cg * 8 + jo) * BB + b] = hi + zbp[(cg * 8 + jo) * BB + b] + bo;
            }
        }
        __syncthreads();
        {
            float iv = zb[zr];
            float fv = zb[zr +  8 * BB];
            float gv = zb[zr + 16 * BB];
            float ov = zb[zr + 24 * BB];
            c1 = fsig(fv) * c1 + fsig(iv) * ftanh(gv);
            __stcg(&h1w[wp][(ub + pu) * BB + pb], fsig(ov) * ftanh(c1));
        }
        target += 64;
        grid_bar(&g_bar[dir], target);

        // ================= Phase B: layer 2 =================
        #pragma unroll
        for (int j = 0; j < 4; j++) acc2[j] = 0ull;
        gemm_pipe(acc2, h1w[wp], HH, W2, ub, htid, b, cg, half,
                  wt0, wt1, ht0, ht1);
        gemm_pipe(acc2, h2w[rp], HH, U2, ub, htid, b, cg, half,
                  wt0, wt1, ht0, ht1);

        if (half == 1) {
            #pragma unroll
            for (int j = 0; j < 4; j++) {
                zbp[(cg * 8 + 2 * j    ) * BB + b] = __int_as_float((int)(acc2[j] & 0xffffffffull));
                zbp[(cg * 8 + 2 * j + 1) * BB + b] = __int_as_float((int)(acc2[j] >> 32));
            }
        }
        __syncthreads();
        if (half == 0) {
            const float* bp0 = (const float*)&b2v0;
            const float* bp1 = (const float*)&b2v1;
            #pragma unroll
            for (int j = 0; j < 4; j++) {
                float lo = __int_as_float((int)(acc2[j] & 0xffffffffull));
                float hi = __int_as_float((int)(acc2[j] >> 32));
                int je = 2 * j, jo = 2 * j + 1;
                float be = (je < 4) ? bp0[je] : bp1[je - 4];
                float bo = (jo < 4) ? bp0[jo] : bp1[jo - 4];
                zb[(cg * 8 + je) * BB + b] = lo + zbp[(cg * 8 + je) * BB + b] + be;
                zb[(cg * 8 + jo) * BB + b] = hi + zbp[(cg * 8 + jo) * BB + b] + bo;
            }
        }
        __syncthreads();
        {
            float iv = zb[zr];
            float fv = zb[zr +  8 * BB];
            float gv = zb[zr + 16 * BB];
            float ov = zb[zr + 24 * BB];
            c2 = fsig(fv) * c2 + fsig(iv) * ftanh(gv);
            __stcg(&h2w[wp][(ub + pu) * BB + pb], fsig(ov) * ftanh(c2));
        }
        target += 64;
        grid_bar(&g_bar[dir], target);
    }
}

// ---------------- final dense head ----------------
__global__ void dense_kernel(const float* __restrict__ Wd, const float* __restrict__ bd,
                             float* __restrict__ out) {
    int tid = threadIdx.x;
    if (tid >= 320) return;
    int bb2 = tid / 5, o = tid % 5;
    float s = bd[o];
    for (int j = 0; j < HH; j++) s += g_h2[0][1][j * BB + bb2] * Wd[j * 5 + o];
    for (int j = 0; j < HH; j++) s += g_h2[1][1][j * BB + bb2] * Wd[(HH + j) * 5 + o];
    out[bb2 * 5 + o] = s;
}

// ---------------- launch ----------------
extern "C" void kernel_launch(void* const* d_in, const int* in_sizes, int n_in,
                              void* d_out, int out_size) {
    const void*  tokens = d_in[0];
    const float* emb = (const float*)d_in[1];
    const float* W1f = (const float*)d_in[2];
    const float* U1f = (const float*)d_in[3];
    const float* b1f = (const float*)d_in[4];
    const float* W2f = (const float*)d_in[5];
    const float* U2f = (const float*)d_in[6];
    const float* b2f = (const float*)d_in[7];
    const float* W1b = (const float*)d_in[8];
    const float* U1b = (const float*)d_in[9];
    const float* b1b = (const float*)d_in[10];
    const float* W2b = (const float*)d_in[11];
    const float* U2b = (const float*)d_in[12];
    const float* b2b = (const float*)d_in[13];
    const float* Wd  = (const float*)d_in[14];
    const float* bd  = (const float*)d_in[15];
    float* out = (float*)d_out;

    cudaFuncSetAttribute(lstm_kernel, cudaFuncAttributeMaxDynamicSharedMemorySize, SMEM_BYTES);

    reset_kernel<<<128, 256>>>();
    detect_kernel<<<1, 256>>>((const unsigned*)tokens);
    dim3 gg(TT, BB);
    gather_kernel<<<gg, 256>>>(tokens, emb);
    lstm_kernel<<<128, 512, SMEM_BYTES>>>(W1f, U1f, b1f, W2f, U2f, b2f,
                                          W1b, U1b, b1b, W2b, U2b, b2b);
    dense_kernel<<<1, 320>>>(Wd, bd, out);
}